// round 1
// baseline (speedup 1.0000x reference)
#include <cuda_runtime.h>

// LTC (liquid time-constant) RNN, B=256 T=8192 I=6 U=64 M=16, 6 ODE unfolds.
// One CTA per batch row (sequential over T). 128 threads:
//   warp w handles units u in [16w,16w+16); lane = (u_lo, q) with q = lane/16
//   selecting the j-half [32q, 32q+32). Per-(j,u) constants in registers.
// sigmoid(x) = 0.5 + 0.5*tanh(0.5x)  -> 1 MUFU.TANH per synapse (MUFU-bound).
// Per-unfold: 32x {LDS(v_j broadcast), FFMA, TANH, FFMA, FFMA}, shfl.bfly(16)
// reduce across the two j-halves, divide, ping-pong v through padded smem
// (addr = j + (j>>5) keeps the two half-warp broadcasts in distinct banks),
// one __syncthreads per unfold.

#define T_LEN 8192
#define NI 6
#define NU 64
#define NM 16

static __device__ __forceinline__ float fast_tanh(float x) {
    float r;
    asm("tanh.approx.f32 %0, %1;" : "=f"(r) : "f"(x));
    return r;
}

__global__ __launch_bounds__(128, 2)
void ltc_kernel(const float* __restrict__ x,
                const float* __restrict__ gleak,
                const float* __restrict__ vleak,
                const float* __restrict__ cm,
                const float* __restrict__ sigma,
                const float* __restrict__ mu,
                const float* __restrict__ w,
                const float* __restrict__ erev,
                const float* __restrict__ s_sigma,
                const float* __restrict__ s_mu,
                const float* __restrict__ s_w,
                const float* __restrict__ s_erev,
                const float* __restrict__ in_w,
                const float* __restrict__ in_b,
                const float* __restrict__ out_w,
                const float* __restrict__ out_b,
                float* __restrict__ out)
{
    __shared__ float vsm[2][68];   // padded: v[j] stored at j + (j>>5)

    const int b    = blockIdx.x;
    const int tid  = threadIdx.x;
    const int lane = tid & 31;
    const int wrp  = tid >> 5;
    const int q    = lane >> 4;              // which j-half this lane covers
    const int u    = (wrp << 4) | (lane & 15);
    const int rbase = q * 33;                // read base after padding

    // per-unit scalars
    const float gl   = gleak[u];
    const float cmt  = cm[u] * 6.0f;         // cm / (elapsed/unfolds) = 6*cm
    const float glvl = gl * vleak[u];
    const float denc = cmt + gl + 1e-8f;     // constant part of den (+eps)

    // per-(j,u) constants for this lane's 32 presynaptic units, in registers:
    //   t2 = 0.5*(v_j - mu)*sigma = v_j*cs + cc ;  contrib uses we = 0.5*w*erev
    //   (|erev| == 1, so 0.5*w == |we|)
    float cs[32], cc[32], cwe[32];
    float Cd = 0.f, Cn = 0.f;                // unfold-invariant 0.5*w sums
#pragma unroll
    for (int jj = 0; jj < 32; jj++) {
        int j   = 32 * q + jj;
        int idx = j * NU + u;
        float s = 0.5f * sigma[idx];
        cs[jj]  = s;
        cc[jj]  = -mu[idx] * s;
        float we = 0.5f * w[idx] * erev[idx];
        cwe[jj] = we;
        Cd += fabsf(we);
        Cn += we;
    }

    // sensory constants: this lane handles inputs i in [3q, 3q+3)
    float ss[3], sc2[3], swe[3], iw[3], ib[3];
    float sCd = 0.f, sCn = 0.f;
#pragma unroll
    for (int i = 0; i < 3; i++) {
        int ii  = 3 * q + i;
        int idx = ii * NU + u;
        float s = 0.5f * s_sigma[idx];
        ss[i]   = s;
        sc2[i]  = -s_mu[idx] * s;
        float we = 0.5f * s_w[idx] * s_erev[idx];
        swe[i]  = we;
        sCd += fabsf(we);
        sCn += we;
        iw[i] = in_w[ii];
        ib[i] = in_b[ii];
    }

    float ow = 0.f, ob = 0.f;
    if (tid < NM) { ow = out_w[tid]; ob = out_b[tid]; }

    if (q == 0) vsm[0][u + (u >> 5)] = 0.f;  // v0 = 0
    float vu = 0.f;

    // x prefetch (double-buffered in registers)
    const float* xb = x + (long long)b * T_LEN * NI + 3 * q;
    float xr0 = xb[0], xr1 = xb[1], xr2 = xb[2];
    float* outp = out + (long long)b * T_LEN * NM;

    __syncthreads();

    for (int t = 0; t < T_LEN; t++) {
        float x0 = xr0, x1 = xr1, x2 = xr2;
        if (t + 1 < T_LEN) {
            const float* xn = xb + (size_t)(t + 1) * NI;
            xr0 = xn[0]; xr1 = xn[1]; xr2 = xn[2];
        }

        // sensory synapses (constant across the 6 unfolds)
        float xi0 = fmaf(x0, iw[0], ib[0]);
        float xi1 = fmaf(x1, iw[1], ib[1]);
        float xi2 = fmaf(x2, iw[2], ib[2]);
        float dsa = sCd, nsa = sCn;
        float h;
        h = fast_tanh(fmaf(xi0, ss[0], sc2[0]));
        dsa = fmaf(fabsf(swe[0]), h, dsa);  nsa = fmaf(swe[0], h, nsa);
        h = fast_tanh(fmaf(xi1, ss[1], sc2[1]));
        dsa = fmaf(fabsf(swe[1]), h, dsa);  nsa = fmaf(swe[1], h, nsa);
        h = fast_tanh(fmaf(xi2, ss[2], sc2[2]));
        dsa = fmaf(fabsf(swe[2]), h, dsa);  nsa = fmaf(swe[2], h, nsa);
        dsa += __shfl_xor_sync(0xffffffffu, dsa, 16);
        nsa += __shfl_xor_sync(0xffffffffu, nsa, 16);
        float den_b = denc + dsa;
        float num_b = glvl + nsa;

        // fused semi-implicit Euler, 6 unfolds, ping-pong v buffers
#pragma unroll 1
        for (int k = 0; k < 6; k++) {
            const float* vr = &vsm[k & 1][rbase];
            float ad = Cd, an = Cn;
#pragma unroll
            for (int jj = 0; jj < 32; jj++) {
                float t2 = fmaf(vr[jj], cs[jj], cc[jj]);
                float hh = fast_tanh(t2);
                ad = fmaf(fabsf(cwe[jj]), hh, ad);
                an = fmaf(cwe[jj], hh, an);
            }
            ad += __shfl_xor_sync(0xffffffffu, ad, 16);
            an += __shfl_xor_sync(0xffffffffu, an, 16);
            float num = fmaf(cmt, vu, num_b + an);
            vu = __fdividef(num, den_b + ad);
            if (q == 0) vsm[(k & 1) ^ 1][u + (u >> 5)] = vu;
            __syncthreads();
        }

        if (tid < NM) outp[(size_t)t * NM + tid] = fmaf(vu, ow, ob);
    }
}

extern "C" void kernel_launch(void* const* d_in, const int* in_sizes, int n_in,
                              void* d_out, int out_size) {
    (void)in_sizes; (void)n_in; (void)out_size;
    ltc_kernel<<<256, 128>>>(
        (const float*)d_in[0],  (const float*)d_in[1],  (const float*)d_in[2],
        (const float*)d_in[3],  (const float*)d_in[4],  (const float*)d_in[5],
        (const float*)d_in[6],  (const float*)d_in[7],  (const float*)d_in[8],
        (const float*)d_in[9],  (const float*)d_in[10], (const float*)d_in[11],
        (const float*)d_in[12], (const float*)d_in[13], (const float*)d_in[14],
        (const float*)d_in[15], (float*)d_out);
}